// round 8
// baseline (speedup 1.0000x reference)
#include <cuda_runtime.h>
#include <math.h>
#include <stdint.h>

#define BSZ 512
#define ENT 512
#define SEQN 64
#define DK 32
#define DF 256
#define DIN 1024
#define NGATE 128
#define ENP1 513

typedef unsigned long long u64;

// ----------------------------- static scratch --------------------------------
__device__ float g_key[(size_t)BSZ * ENT * DK];
__device__ float g_selkey[(size_t)BSZ * SEQN * DK];
__device__ int   g_removed[(size_t)BSZ * ENP1];
__device__ float g_selemb[(size_t)SEQN * BSZ * DK];
__device__ float g_base[(size_t)BSZ * DF];
__device__ float g_W2[(size_t)DF * DF];
__device__ float g_c2[DF];
__device__ float g_gx[(size_t)SEQN * BSZ * NGATE];
__device__ float g_q[(size_t)SEQN * BSZ * DK];

// ----------------------------- helpers ---------------------------------------
__device__ __forceinline__ float wredsum(float v) {
#pragma unroll
    for (int o = 16; o; o >>= 1) v += __shfl_xor_sync(0xffffffffu, v, o);
    return v;
}
__device__ __forceinline__ void fma2(u64& d, u64 a, u64 b) {
    asm("fma.rn.f32x2 %0,%1,%2,%0;" : "+l"(d) : "l"(a), "l"(b));
}
__device__ __forceinline__ float2 up2(u64 v) {
    float2 f;
    asm("mov.b64 {%0,%1},%2;" : "=f"(f.x), "=f"(f.y) : "l"(v));
    return f;
}
__device__ __forceinline__ uint32_t f2tf(float f) {
    uint32_t r;
    asm("cvt.rna.tf32.f32 %0, %1;" : "=r"(r) : "f"(f));
    return r;
}
__device__ __forceinline__ void mma_tf32(float* c, uint32_t a0, uint32_t a1, uint32_t a2,
                                         uint32_t a3, uint32_t b0, uint32_t b1) {
    asm volatile(
        "mma.sync.aligned.m16n8k8.row.col.f32.tf32.tf32.f32 "
        "{%0,%1,%2,%3},{%4,%5,%6,%7},{%8,%9},{%0,%1,%2,%3};"
        : "+f"(c[0]), "+f"(c[1]), "+f"(c[2]), "+f"(c[3])
        : "r"(a0), "r"(a1), "r"(a2), "r"(a3), "r"(b0), "r"(b1));
}

// --------------- tf32 tensor-core GEMM (standalone) ---------------------------
// EPI: 0 plain | 1 +bias | 2 +bias & end-scatter (key)
template <int BN, int EPI>
__global__ void k_mma(const float* __restrict__ A, const float* __restrict__ B,
                      const float* __restrict__ bias, float* __restrict__ C,
                      int K, int N, const float* __restrict__ xb,
                      const int* __restrict__ xi) {
    constexpr int BM = 64, KC = 32;
    constexpr int NBLD = (KC * BN) / 1024;
    constexpr int NT = BN / 16;
    __shared__ uint32_t As[BM][KC + 4];
    __shared__ uint32_t Bs[KC][BN + 4];
    const int t = threadIdx.x;
    const int wid = t >> 5, lane = t & 31;
    const int gid = lane >> 2, tig = lane & 3;
    const int warpM = wid & 3, warpN = wid >> 2;
    const int m0 = blockIdx.x * BM;
    const int n0 = blockIdx.y * BN;

    float cr[NT][4];
#pragma unroll
    for (int j = 0; j < NT; j++) {
        cr[j][0] = 0.f; cr[j][1] = 0.f; cr[j][2] = 0.f; cr[j][3] = 0.f;
    }

    const int ar0 = t >> 3;
    const int ak = (t & 7) * 4;
    constexpr int BQ = BN / 4;
    const int br0 = t / BQ;
    const int bn = (t % BQ) * 4;

    float4 pa0, pa1, pb[NBLD];
    pa0 = *(const float4*)&A[(size_t)(m0 + ar0) * K + ak];
    pa1 = *(const float4*)&A[(size_t)(m0 + ar0 + 32) * K + ak];
#pragma unroll
    for (int i = 0; i < NBLD; i++) {
        int kr = br0 + i * (256 / BQ);
        pb[i] = *(const float4*)&B[(size_t)kr * N + n0 + bn];
    }

    const int nch = K / KC;
    for (int ch = 0; ch < nch; ch++) {
        __syncthreads();
        {
            uint4 q;
            q.x = f2tf(pa0.x); q.y = f2tf(pa0.y); q.z = f2tf(pa0.z); q.w = f2tf(pa0.w);
            *(uint4*)&As[ar0][ak] = q;
            q.x = f2tf(pa1.x); q.y = f2tf(pa1.y); q.z = f2tf(pa1.z); q.w = f2tf(pa1.w);
            *(uint4*)&As[ar0 + 32][ak] = q;
#pragma unroll
            for (int i = 0; i < NBLD; i++) {
                int kr = br0 + i * (256 / BQ);
                q.x = f2tf(pb[i].x); q.y = f2tf(pb[i].y);
                q.z = f2tf(pb[i].z); q.w = f2tf(pb[i].w);
                *(uint4*)&Bs[kr][bn] = q;
            }
        }
        if (ch + 1 < nch) {
            int k0 = (ch + 1) * KC;
            pa0 = *(const float4*)&A[(size_t)(m0 + ar0) * K + k0 + ak];
            pa1 = *(const float4*)&A[(size_t)(m0 + ar0 + 32) * K + k0 + ak];
#pragma unroll
            for (int i = 0; i < NBLD; i++) {
                int kr = k0 + br0 + i * (256 / BQ);
                pb[i] = *(const float4*)&B[(size_t)kr * N + n0 + bn];
            }
        }
        __syncthreads();
#pragma unroll
        for (int kk = 0; kk < KC; kk += 8) {
            uint32_t a0 = As[warpM * 16 + gid][kk + tig];
            uint32_t a1 = As[warpM * 16 + gid + 8][kk + tig];
            uint32_t a2 = As[warpM * 16 + gid][kk + tig + 4];
            uint32_t a3 = As[warpM * 16 + gid + 8][kk + tig + 4];
#pragma unroll
            for (int j = 0; j < NT; j++) {
                int nb = warpN * (BN / 2) + j * 8;
                uint32_t b0 = Bs[kk + tig][nb + gid];
                uint32_t b1 = Bs[kk + tig + 4][nb + gid];
                mma_tf32(cr[j], a0, a1, a2, a3, b0, b1);
            }
        }
    }

    const int rb = m0 + warpM * 16 + gid;
#pragma unroll
    for (int j = 0; j < NT; j++) {
        int cb = n0 + warpN * (BN / 2) + j * 8 + tig * 2;
#pragma unroll
        for (int h = 0; h < 2; h++) {
            int m = rb + h * 8;
            float v0 = cr[j][h * 2 + 0];
            float v1 = cr[j][h * 2 + 1];
            if (EPI == 0) {
                C[(size_t)m * N + cb] = v0;
                C[(size_t)m * N + cb + 1] = v1;
            } else if (EPI == 1) {
                C[(size_t)m * N + cb] = v0 + bias[cb];
                C[(size_t)m * N + cb + 1] = v1 + bias[cb + 1];
            } else if (EPI == 2) {
                int en = xi[m0 >> 9];
                if ((m & 511) == en) {
                    C[(size_t)m * N + cb] = xb[cb];
                    C[(size_t)m * N + cb + 1] = xb[cb + 1];
                } else {
                    C[(size_t)m * N + cb] = v0 + bias[cb];
                    C[(size_t)m * N + cb + 1] = v1 + bias[cb + 1];
                }
            }
        }
    }
}

// --------------- selected-key gathered GEMM + removed scatter ------------------
// block b: selkey[b][j] = ent[b, sel[b,j]] @ key_w + key_b  (j = 0..63)
__global__ void __launch_bounds__(256) k_selkey(const float* __restrict__ ent,
                                                const float* __restrict__ kw,
                                                const float* __restrict__ kb,
                                                const int* __restrict__ sel) {
    __shared__ uint32_t AS[64 * 68];
    __shared__ uint32_t BS[64 * 36];
    __shared__ int ssh[64];
    const int t = threadIdx.x;
    const int b = blockIdx.x;
    const int wid = t >> 5, lane = t & 31;
    const int gid = lane >> 2, tig = lane & 3;
    const int warpM = wid & 3, warpN = wid >> 2;

    if (t < 64) ssh[t] = sel[b * SEQN + t];
    for (int n = t; n < ENP1; n += 256) g_removed[(size_t)b * ENP1 + n] = 65;
    __syncthreads();
    if (t < 64) atomicMin(&g_removed[(size_t)b * ENP1 + ssh[t]], t + 1);

    float acc[2][4];
    acc[0][0] = acc[0][1] = acc[0][2] = acc[0][3] = 0.f;
    acc[1][0] = acc[1][1] = acc[1][2] = acc[1][3] = 0.f;

    for (int ch = 0; ch < 4; ch++) {
        int k0 = ch * 64;
        __syncthreads();
#pragma unroll
        for (int p = 0; p < 4; p++) {
            int idx = t + p * 256;
            int r = idx >> 4, c4 = (idx & 15) * 4;
            float4 v = *(const float4*)&ent[((size_t)b * ENT + ssh[r]) * 256 + k0 + c4];
            AS[r * 68 + c4 + 0] = f2tf(v.x);
            AS[r * 68 + c4 + 1] = f2tf(v.y);
            AS[r * 68 + c4 + 2] = f2tf(v.z);
            AS[r * 68 + c4 + 3] = f2tf(v.w);
        }
#pragma unroll
        for (int p = 0; p < 2; p++) {
            int idx = t + p * 256;
            int r = idx >> 3, c4 = (idx & 7) * 4;
            float4 v = *(const float4*)&kw[(size_t)(k0 + r) * 32 + c4];
            BS[r * 36 + c4 + 0] = f2tf(v.x);
            BS[r * 36 + c4 + 1] = f2tf(v.y);
            BS[r * 36 + c4 + 2] = f2tf(v.z);
            BS[r * 36 + c4 + 3] = f2tf(v.w);
        }
        __syncthreads();
#pragma unroll
        for (int kk = 0; kk < 64; kk += 8) {
            uint32_t a0 = AS[(warpM * 16 + gid) * 68 + kk + tig];
            uint32_t a1 = AS[(warpM * 16 + gid + 8) * 68 + kk + tig];
            uint32_t a2 = AS[(warpM * 16 + gid) * 68 + kk + tig + 4];
            uint32_t a3 = AS[(warpM * 16 + gid + 8) * 68 + kk + tig + 4];
#pragma unroll
            for (int j = 0; j < 2; j++) {
                int nb = warpN * 16 + j * 8;
                uint32_t b0 = BS[(kk + tig) * 36 + nb + gid];
                uint32_t b1 = BS[(kk + tig + 4) * 36 + nb + gid];
                mma_tf32(acc[j], a0, a1, a2, a3, b0, b1);
            }
        }
    }
#pragma unroll
    for (int j = 0; j < 2; j++) {
        int cb = warpN * 16 + j * 8 + tig * 2;
        float b0 = kb[cb], b1 = kb[cb + 1];
#pragma unroll
        for (int h = 0; h < 2; h++) {
            int r = warpM * 16 + gid + h * 8;
            g_selkey[((size_t)b * SEQN + r) * DK + cb] = acc[j][h * 2] + b0;
            g_selkey[((size_t)b * SEQN + r) * DK + cb + 1] = acc[j][h * 2 + 1] + b1;
        }
    }
}

// --------------- mega-fused: selemb -> u -> P -> relu -> x -> LN gates --------
#define SMF 44288
__global__ void __launch_bounds__(256, 1)
k_fused(const float* __restrict__ e1w, const float* __restrict__ e1b,
        const float* __restrict__ q2w, const float* __restrict__ q2b,
        const float* __restrict__ wih, const float* __restrict__ ln_ig,
        const float* __restrict__ ln_ib) {
    extern __shared__ float sm[];
    uint32_t* U = (uint32_t*)sm;
    uint32_t* BSb = (uint32_t*)(sm + 16640);
    uint32_t* Q2S = (uint32_t*)(sm + 16640);
    float* xsh = sm + 26880;
    float* wsh = sm + 28992;
    uint32_t* E1 = (uint32_t*)(sm + 33536);
    uint32_t* SEL = (uint32_t*)(sm + 41984);

    const int t = threadIdx.x;
    const int wid = t >> 5, lane = t & 31;
    const int gid = lane >> 2, tig = lane & 3;
    const int warpM = wid & 3, warpN = wid >> 2;
    const int m0 = blockIdx.x * 64;
    const int step = m0 >> 9;
    const int b0 = m0 & 511;

    if (step == 0) {
        for (int idx = t; idx < 64 * 256; idx += 256) {
            int r = idx >> 8, c = idx & 255;
            U[r * 260 + c] = f2tf(fmaxf(g_base[(size_t)(b0 + r) * 256 + c], 0.f));
        }
    } else {
        for (int idx = t; idx < 512; idx += 256) {
            int r = idx >> 3, c4 = (idx & 7) * 4;
            float4 v = *(const float4*)&g_selemb[(size_t)(m0 - 512 + r) * 32 + c4];
            SEL[r * 36 + c4 + 0] = f2tf(v.x);
            SEL[r * 36 + c4 + 1] = f2tf(v.y);
            SEL[r * 36 + c4 + 2] = f2tf(v.z);
            SEL[r * 36 + c4 + 3] = f2tf(v.w);
        }
        for (int idx = t; idx < 2048; idx += 256) {
            int r = idx >> 6, c4 = (idx & 63) * 4;
            float4 v = *(const float4*)&e1w[(size_t)r * 256 + c4];
            E1[r * 264 + c4 + 0] = f2tf(v.x);
            E1[r * 264 + c4 + 1] = f2tf(v.y);
            E1[r * 264 + c4 + 2] = f2tf(v.z);
            E1[r * 264 + c4 + 3] = f2tf(v.w);
        }
        __syncthreads();

        float acc[16][4];
#pragma unroll
        for (int j = 0; j < 16; j++) {
            acc[j][0] = 0.f; acc[j][1] = 0.f; acc[j][2] = 0.f; acc[j][3] = 0.f;
        }
#pragma unroll
        for (int kk = 0; kk < 32; kk += 8) {
            uint32_t a0 = SEL[(warpM * 16 + gid) * 36 + kk + tig];
            uint32_t a1 = SEL[(warpM * 16 + gid + 8) * 36 + kk + tig];
            uint32_t a2 = SEL[(warpM * 16 + gid) * 36 + kk + tig + 4];
            uint32_t a3 = SEL[(warpM * 16 + gid + 8) * 36 + kk + tig + 4];
#pragma unroll
            for (int j = 0; j < 16; j++) {
                int nb = warpN * 128 + j * 8;
                uint32_t b0 = E1[(kk + tig) * 264 + nb + gid];
                uint32_t b1 = E1[(kk + tig + 4) * 264 + nb + gid];
                mma_tf32(acc[j], a0, a1, a2, a3, b0, b1);
            }
        }
#pragma unroll
        for (int j = 0; j < 16; j++) {
            int cb = warpN * 128 + j * 8 + tig * 2;
            float bb0 = e1b[cb], bb1 = e1b[cb + 1];
#pragma unroll
            for (int h = 0; h < 2; h++) {
                int r = warpM * 16 + gid + h * 8;
                U[r * 260 + cb] = f2tf(fmaxf(acc[j][h * 2] + bb0, 0.f));
                U[r * 260 + cb + 1] = f2tf(fmaxf(acc[j][h * 2 + 1] + bb1, 0.f));
            }
        }
#pragma unroll
        for (int j = 0; j < 16; j++) {
            acc[j][0] = 0.f; acc[j][1] = 0.f; acc[j][2] = 0.f; acc[j][3] = 0.f;
        }
        float4 pw[8];
#pragma unroll
        for (int p = 0; p < 8; p++) {
            int idx = t + p * 256;
            int r = idx >> 6, c4 = (idx & 63) * 4;
            pw[p] = *(const float4*)&g_W2[(size_t)r * 256 + c4];
        }
        for (int ch = 0; ch < 8; ch++) {
            int buf = ch & 1;
            uint32_t* BS = BSb + buf * 8448;
#pragma unroll
            for (int p = 0; p < 8; p++) {
                int idx = t + p * 256;
                int r = idx >> 6, c4 = (idx & 63) * 4;
                BS[r * 264 + c4 + 0] = f2tf(pw[p].x);
                BS[r * 264 + c4 + 1] = f2tf(pw[p].y);
                BS[r * 264 + c4 + 2] = f2tf(pw[p].z);
                BS[r * 264 + c4 + 3] = f2tf(pw[p].w);
            }
            if (ch + 1 < 8) {
#pragma unroll
                for (int p = 0; p < 8; p++) {
                    int idx = t + p * 256;
                    int r = idx >> 6, c4 = (idx & 63) * 4;
                    pw[p] = *(const float4*)&g_W2[(size_t)((ch + 1) * 32 + r) * 256 + c4];
                }
            }
            __syncthreads();
#pragma unroll
            for (int kk = 0; kk < 32; kk += 8) {
                int kg = ch * 32 + kk;
                uint32_t a0 = U[(warpM * 16 + gid) * 260 + kg + tig];
                uint32_t a1 = U[(warpM * 16 + gid + 8) * 260 + kg + tig];
                uint32_t a2 = U[(warpM * 16 + gid) * 260 + kg + tig + 4];
                uint32_t a3 = U[(warpM * 16 + gid + 8) * 260 + kg + tig + 4];
#pragma unroll
                for (int j = 0; j < 16; j++) {
                    int nb = warpN * 128 + j * 8;
                    uint32_t b0 = BS[(kk + tig) * 264 + nb + gid];
                    uint32_t b1 = BS[(kk + tig + 4) * 264 + nb + gid];
                    mma_tf32(acc[j], a0, a1, a2, a3, b0, b1);
                }
            }
            __syncthreads();
        }
#pragma unroll
        for (int j = 0; j < 16; j++) {
            int cb = warpN * 128 + j * 8 + tig * 2;
            float cc0 = g_c2[cb], cc1 = g_c2[cb + 1];
#pragma unroll
            for (int h = 0; h < 2; h++) {
                int r = warpM * 16 + gid + h * 8;
                float bs0 = g_base[(size_t)(b0 + r) * 256 + cb];
                float bs1 = g_base[(size_t)(b0 + r) * 256 + cb + 1];
                U[r * 260 + cb] = f2tf(fmaxf(acc[j][h * 2] + bs0 + cc0, 0.f));
                U[r * 260 + cb + 1] = f2tf(fmaxf(acc[j][h * 2 + 1] + bs1 + cc1, 0.f));
            }
        }
    }
    __syncthreads();

    for (int idx = t; idx < 2048; idx += 256) {
        int r = idx >> 3, c4 = (idx & 7) * 4;
        float4 v = *(const float4*)&q2w[(size_t)r * 32 + c4];
        Q2S[r * 40 + c4 + 0] = f2tf(v.x);
        Q2S[r * 40 + c4 + 1] = f2tf(v.y);
        Q2S[r * 40 + c4 + 2] = f2tf(v.z);
        Q2S[r * 40 + c4 + 3] = f2tf(v.w);
    }
    for (int idx = t; idx < 4096; idx += 256) wsh[idx] = wih[idx];
    __syncthreads();

    {
        float ax[2][4];
        ax[0][0] = ax[0][1] = ax[0][2] = ax[0][3] = 0.f;
        ax[1][0] = ax[1][1] = ax[1][2] = ax[1][3] = 0.f;
#pragma unroll 4
        for (int kk = 0; kk < 256; kk += 8) {
            uint32_t a0 = U[(warpM * 16 + gid) * 260 + kk + tig];
            uint32_t a1 = U[(warpM * 16 + gid + 8) * 260 + kk + tig];
            uint32_t a2 = U[(warpM * 16 + gid) * 260 + kk + tig + 4];
            uint32_t a3 = U[(warpM * 16 + gid + 8) * 260 + kk + tig + 4];
#pragma unroll
            for (int j = 0; j < 2; j++) {
                int nb = warpN * 16 + j * 8;
                uint32_t b0 = Q2S[(kk + tig) * 40 + nb + gid];
                uint32_t b1 = Q2S[(kk + tig + 4) * 40 + nb + gid];
                mma_tf32(ax[j], a0, a1, a2, a3, b0, b1);
            }
        }
        __syncthreads();
#pragma unroll
        for (int j = 0; j < 2; j++) {
            int cb = warpN * 16 + j * 8 + tig * 2;
            float qb0 = q2b[cb], qb1 = q2b[cb + 1];
#pragma unroll
            for (int h = 0; h < 2; h++) {
                int r = warpM * 16 + gid + h * 8;
                xsh[r * 33 + cb] = ax[j][h * 2] + qb0;
                xsh[r * 33 + cb + 1] = ax[j][h * 2 + 1] + qb1;
            }
        }
    }
    __syncthreads();

    {
        int w = wid;
        float lg[4], lb[4];
#pragma unroll
        for (int g = 0; g < 4; g++) {
            lg[g] = ln_ig[g * 32 + lane];
            lb[g] = ln_ib[g * 32 + lane];
        }
        for (int rr = 0; rr < 8; rr++) {
            int row = rr * 8 + w;
            float xv = xsh[row * 33 + lane];
            float acg[4] = {0.f, 0.f, 0.f, 0.f};
#pragma unroll
            for (int k = 0; k < 32; k++) {
                float xk = __shfl_sync(0xffffffffu, xv, k);
#pragma unroll
                for (int g = 0; g < 4; g++) acg[g] += xk * wsh[k * 128 + g * 32 + lane];
            }
            float s = acg[0] + acg[1] + acg[2] + acg[3];
            float m = wredsum(s) * (1.f / 128.f);
            float vs = 0.f;
#pragma unroll
            for (int g = 0; g < 4; g++) {
                float d = acg[g] - m;
                vs += d * d;
            }
            float v = wredsum(vs) * (1.f / 128.f);
            float rs = rsqrtf(v + 1e-5f);
#pragma unroll
            for (int g = 0; g < 4; g++)
                g_gx[(size_t)(m0 + row) * 128 + g * 32 + lane] =
                    (acg[g] - m) * rs * lg[g] + lb[g];
        }
    }
}

// ------------------- per-step pooled embedding (reads selkey) ------------------
__global__ void k_emb(const int* __restrict__ sel, const int* __restrict__ en_arr,
                      const int* __restrict__ selnum) {
    int t = threadIdx.x;
    int lane = t & 31;
    int b = blockIdx.x * 8 + (t >> 5);
    int en = en_arr[b];
    int sn = selnum[b];
    int s0 = sel[b * SEQN + lane];
    int s1 = sel[b * SEQN + 32 + lane];
    int sc = __shfl_sync(0xffffffffu, s0, 0);
    float kv_n = g_selkey[((size_t)b * SEQN + 0) * DK + lane];
    int rm_n = g_removed[(size_t)b * ENP1 + sc];
    float sum = 0.f;
    int cnt = 0;
    bool endf = false;
    for (int j = 0; j < SEQN; j++) {
        float kv = kv_n;
        int rm = rm_n;
        int s = (j < 32) ? __shfl_sync(0xffffffffu, s0, j) : __shfl_sync(0xffffffffu, s1, j - 32);
        if (j + 1 < SEQN) {
            int s2 = (j + 1 < 32) ? __shfl_sync(0xffffffffu, s0, j + 1)
                                  : __shfl_sync(0xffffffffu, s1, j - 31);
            kv_n = g_selkey[((size_t)b * SEQN + j + 1) * DK + lane];
            rm_n = g_removed[(size_t)b * ENP1 + s2];
        }
        endf = endf || (s == en);
        if ((!endf) && rm == j + 1) {
            sum += kv;
            cnt++;
        }
        float denom = (sn != 0 && cnt > 0) ? (float)cnt : 1.f;
        g_selemb[((size_t)j * BSZ + b) * DK + lane] = sum / denom;
    }
}

// ------------------- c2 = e2_b @ q1_w ------------------------------------------
__global__ void k_c2(const float* __restrict__ e2b, const float* __restrict__ q1w) {
    int t = threadIdx.x;
    float acc = 0.f;
    for (int k = 0; k < DIN; k++) acc += e2b[k] * q1w[(size_t)k * DF + t];
    g_c2[t] = acc;
}

// ------------------- sequential LN-LSTM (warp/batch) ---------------------------
__global__ void k_lstm(const float* __restrict__ whh, const float* __restrict__ ln_hg,
                       const float* __restrict__ ln_hb, const float* __restrict__ ln_cg,
                       const float* __restrict__ ln_cb) {
    __shared__ float wsh[32 * 128];
    int t = threadIdx.x;
    for (int idx = t; idx < 4096; idx += 256) wsh[idx] = whh[idx];
    __syncthreads();
    int lane = t & 31, w = t >> 5;
    int b = blockIdx.x * 8 + w;
    float h = 0.f, c = 0.f;
    float hg[4], hb[4];
#pragma unroll
    for (int g = 0; g < 4; g++) {
        int cc = g * 32 + lane;
        hg[g] = ln_hg[cc];
        hb[g] = ln_hb[cc];
    }
    float cgm = ln_cg[lane], cbm = ln_cb[lane];
    float gxr[4];
#pragma unroll
    for (int g = 0; g < 4; g++) gxr[g] = g_gx[(size_t)b * 128 + g * 32 + lane];
    for (int i = 0; i < SEQN; i++) {
        float gxn[4];
        if (i + 1 < SEQN) {
            size_t rn = (size_t)(i + 1) * BSZ + b;
#pragma unroll
            for (int g = 0; g < 4; g++) gxn[g] = g_gx[rn * 128 + g * 32 + lane];
        }
        float acc[4] = {0.f, 0.f, 0.f, 0.f};
#pragma unroll
        for (int k = 0; k < 32; k++) {
            float hk = __shfl_sync(0xffffffffu, h, k);
#pragma unroll
            for (int g = 0; g < 4; g++) acc[g] += hk * wsh[k * 128 + g * 32 + lane];
        }
        float s = acc[0] + acc[1] + acc[2] + acc[3];
        float m = wredsum(s) * (1.f / 128.f);
        float vs = 0.f;
#pragma unroll
        for (int g = 0; g < 4; g++) {
            float d = acc[g] - m;
            vs += d * d;
        }
        float v = wredsum(vs) * (1.f / 128.f);
        float rs = rsqrtf(v + 1e-5f);
        float gate[4];
#pragma unroll
        for (int g = 0; g < 4; g++) gate[g] = gxr[g] + (acc[g] - m) * rs * hg[g] + hb[g];
        float ii = 1.f / (1.f + __expf(-gate[0]));
        float ff = 1.f / (1.f + __expf(-gate[1]));
        float gg = tanhf(gate[2]);
        float oo = 1.f / (1.f + __expf(-gate[3]));
        float cn = ff * c + ii * gg;
        float mc = wredsum(cn) * (1.f / 32.f);
        float dc = cn - mc;
        float vc = wredsum(dc * dc) * (1.f / 32.f);
        c = dc * rsqrtf(vc + 1e-5f) * cgm + cbm;
        h = oo * tanhf(c);
        g_q[((size_t)i * BSZ + b) * DK + lane] = h;
#pragma unroll
        for (int g = 0; g < 4; g++) gxr[g] = gxn[g];
    }
}

// ------------------- logits + mask (grid BSZ x 2) -------------------------------
__global__ void k_logits(const int* __restrict__ en_arr, float* __restrict__ out) {
    __shared__ float Qsh[64 * 32];
    __shared__ float Ksh[256 * 34];
    __shared__ int rsh[256];
    typedef unsigned long long u64l;
    int t = threadIdx.x;
    int b = blockIdx.x;
    int tile = blockIdx.y;
    int en = en_arr[b];
    for (int idx = t; idx < 2048; idx += 256) {
        int s = idx >> 5, k = idx & 31;
        Qsh[idx] = g_q[((size_t)s * BSZ + b) * 32 + k];
    }
    const u64l* Q2 = (const u64l*)Qsh;
    int n0 = tile * 256;
    for (int idx = t; idx < 8192; idx += 256) {
        int n = idx >> 5, k = idx & 31;
        Ksh[n * 34 + k] = g_key[((size_t)b * ENT + n0 + n) * 32 + k];
    }
    rsh[t] = g_removed[(size_t)b * ENP1 + n0 + t];
    __syncthreads();
    u64l kreg[16];
#pragma unroll
    for (int kp = 0; kp < 16; kp++) {
        float2 kk = *(const float2*)&Ksh[t * 34 + kp * 2];
        asm("mov.b64 %0,{%1,%2};" : "=l"(kreg[kp]) : "f"(kk.x), "f"(kk.y));
    }
    int rstep = rsh[t];
    int n = n0 + t;
    for (int s = 0; s < SEQN; s++) {
        u64l a0 = 0ull, a1 = 0ull;
#pragma unroll
        for (int kp = 0; kp < 16; kp += 2) {
            fma2(a0, kreg[kp], Q2[s * 16 + kp]);
            fma2(a1, kreg[kp + 1], Q2[s * 16 + kp + 1]);
        }
        float2 f0 = up2(a0), f1 = up2(a1);
        float dot = (f0.x + f0.y) + (f1.x + f1.y);
        bool keep = (n < en) ? (rstep > s) : ((n == en) ? (s >= 1 && rstep > s) : false);
        out[((size_t)b * SEQN + s) * ENP1 + n] = keep ? dot : -1e9f;
    }
    if (tile == 1 && t < SEQN) out[((size_t)b * SEQN + t) * ENP1 + 512] = -1e9f;
}

// ------------------------------- launch ----------------------------------------
extern "C" void kernel_launch(void* const* d_in, const int* in_sizes, int n_in,
                              void* d_out, int out_size) {
    const float* ent = (const float*)d_in[0];
    const float* ar = (const float*)d_in[1];
    const int* entity_num = (const int*)d_in[2];
    const int* sel = (const int*)d_in[3];
    const int* selnum = (const int*)d_in[4];
    const float* key_w = (const float*)d_in[5];
    const float* key_b = (const float*)d_in[6];
    const float* q1w = (const float*)d_in[7];
    const float* q1b = (const float*)d_in[8];
    const float* q2w = (const float*)d_in[9];
    const float* q2b = (const float*)d_in[10];
    const float* e1w = (const float*)d_in[11];
    const float* e1b = (const float*)d_in[12];
    const float* e2w = (const float*)d_in[13];
    const float* e2b = (const float*)d_in[14];
    const float* endv = (const float*)d_in[15];
    const float* wih = (const float*)d_in[16];
    const float* whh = (const float*)d_in[17];
    const float* ln_ig = (const float*)d_in[18];
    const float* ln_ib = (const float*)d_in[19];
    const float* ln_hg = (const float*)d_in[20];
    const float* ln_hb = (const float*)d_in[21];
    const float* ln_cg = (const float*)d_in[22];
    const float* ln_cb = (const float*)d_in[23];
    float* out = (float*)d_out;

    void *pKey, *pBase, *pW2;
    cudaGetSymbolAddress(&pKey, g_key);
    cudaGetSymbolAddress(&pBase, g_base);
    cudaGetSymbolAddress(&pW2, g_W2);

    static cudaStream_t sB = 0, sC = 0, sD = 0;
    static cudaEvent_t eFork = 0, eB = 0, eW2 = 0, eKey = 0;
    if (!sB) {
        cudaStreamCreateWithFlags(&sB, cudaStreamNonBlocking);
        cudaStreamCreateWithFlags(&sC, cudaStreamNonBlocking);
        cudaStreamCreateWithFlags(&sD, cudaStreamNonBlocking);
        cudaEventCreateWithFlags(&eFork, cudaEventDisableTiming);
        cudaEventCreateWithFlags(&eB, cudaEventDisableTiming);
        cudaEventCreateWithFlags(&eW2, cudaEventDisableTiming);
        cudaEventCreateWithFlags(&eKey, cudaEventDisableTiming);
        cudaFuncSetAttribute(k_fused, cudaFuncAttributeMaxDynamicSharedMemorySize,
                             SMF * 4);
    }

    // fork
    cudaEventRecord(eFork, 0);
    cudaStreamWaitEvent(sB, eFork, 0);
    cudaStreamWaitEvent(sC, eFork, 0);
    cudaStreamWaitEvent(sD, eFork, 0);

    // side B: c2 + base
    k_c2<<<1, 256, 0, sB>>>(e2b, q1w);
    k_mma<64, 1><<<dim3(BSZ / 64, DF / 64), 256, 0, sB>>>(
        ar, q1w, q1b, (float*)pBase, DIN, DF, nullptr, nullptr);
    cudaEventRecord(eB, sB);

    // side C: W2 = e2 @ q1
    k_mma<64, 0><<<dim3(DF / 64, DF / 64), 256, 0, sC>>>(
        e2w, q1w, nullptr, (float*)pW2, DIN, DF, nullptr, nullptr);
    cudaEventRecord(eW2, sC);

    // side D: full key GEMM (only logits needs it)
    k_mma<32, 2><<<dim3(BSZ * ENT / 64, 1), 256, 0, sD>>>(
        ent, key_w, key_b, (float*)pKey, DF, DK, endv, entity_num);
    cudaEventRecord(eKey, sD);

    // main: selkey (+removed) -> emb -> fused -> lstm -> logits
    k_selkey<<<BSZ, 256>>>(ent, key_w, key_b, sel);
    k_emb<<<BSZ / 8, 256>>>(sel, entity_num, selnum);
    cudaStreamWaitEvent(0, eB, 0);
    cudaStreamWaitEvent(0, eW2, 0);
    k_fused<<<SEQN * BSZ / 64, 256, SMF * 4>>>(e1w, e1b, q2w, q2b, wih, ln_ig, ln_ib);
    k_lstm<<<BSZ / 8, 256>>>(whh, ln_hg, ln_hb, ln_cg, ln_cb);
    cudaStreamWaitEvent(0, eKey, 0);
    k_logits<<<dim3(BSZ, 2), 256>>>(entity_num, out);
    (void)in_sizes;
    (void)n_in;
    (void)out_size;
}

// round 9
// speedup vs baseline: 1.1383x; 1.1383x over previous
#include <cuda_runtime.h>
#include <math.h>
#include <stdint.h>

#define BSZ 512
#define ENT 512
#define SEQN 64
#define DK 32
#define DF 256
#define DIN 1024
#define NGATE 128
#define ENP1 513

typedef unsigned long long u64;

// ----------------------------- static scratch --------------------------------
__device__ float g_key[(size_t)BSZ * ENT * DK];
__device__ int   g_removed[(size_t)BSZ * ENP1];
__device__ float g_selemb[(size_t)SEQN * BSZ * DK];
__device__ float g_base[(size_t)BSZ * DF];
__device__ float g_basec[(size_t)BSZ * DF];   // base + c2
__device__ float g_W2[(size_t)DF * DF];       // holds tf32 BITS (written by EPI 6)
__device__ float g_c2[DF];
__device__ uint32_t g_e1t[32 * 256];          // e1w as tf32 bits
__device__ uint32_t g_q2t[256 * 32];          // q2w as tf32 bits
__device__ float g_gx[(size_t)SEQN * BSZ * NGATE];
__device__ float g_q[(size_t)SEQN * BSZ * DK];

// ----------------------------- helpers ---------------------------------------
__device__ __forceinline__ float wredsum(float v) {
#pragma unroll
    for (int o = 16; o; o >>= 1) v += __shfl_xor_sync(0xffffffffu, v, o);
    return v;
}
__device__ __forceinline__ void fma2(u64& d, u64 a, u64 b) {
    asm("fma.rn.f32x2 %0,%1,%2,%0;" : "+l"(d) : "l"(a), "l"(b));
}
__device__ __forceinline__ float2 up2(u64 v) {
    float2 f;
    asm("mov.b64 {%0,%1},%2;" : "=f"(f.x), "=f"(f.y) : "l"(v));
    return f;
}
__device__ __forceinline__ uint32_t f2tf(float f) {
    uint32_t r;
    asm("cvt.rna.tf32.f32 %0, %1;" : "=r"(r) : "f"(f));
    return r;
}
__device__ __forceinline__ void mma_tf32(float* c, uint32_t a0, uint32_t a1, uint32_t a2,
                                         uint32_t a3, uint32_t b0, uint32_t b1) {
    asm volatile(
        "mma.sync.aligned.m16n8k8.row.col.f32.tf32.tf32.f32 "
        "{%0,%1,%2,%3},{%4,%5,%6,%7},{%8,%9},{%0,%1,%2,%3};"
        : "+f"(c[0]), "+f"(c[1]), "+f"(c[2]), "+f"(c[3])
        : "r"(a0), "r"(a1), "r"(a2), "r"(a3), "r"(b0), "r"(b1));
}

// --------------- tf32 tensor-core GEMM (standalone) ---------------------------
// EPI: 2 +bias & end-scatter (key) | 6 plain -> C as tf32 BITS | 7 +bias -> C, +xb -> C2
template <int BN, int EPI>
__global__ void k_mma(const float* __restrict__ A, const float* __restrict__ B,
                      const float* __restrict__ bias, float* __restrict__ C,
                      int K, int N, const float* __restrict__ xb,
                      const int* __restrict__ xi, float* __restrict__ C2) {
    constexpr int BM = 64, KC = 32;
    constexpr int NBLD = (KC * BN) / 1024;
    constexpr int NT = BN / 16;
    __shared__ uint32_t As[BM][KC + 4];
    __shared__ uint32_t Bs[KC][BN + 4];
    const int t = threadIdx.x;
    const int wid = t >> 5, lane = t & 31;
    const int gid = lane >> 2, tig = lane & 3;
    const int warpM = wid & 3, warpN = wid >> 2;
    const int m0 = blockIdx.x * BM;
    const int n0 = blockIdx.y * BN;

    float cr[NT][4];
#pragma unroll
    for (int j = 0; j < NT; j++) {
        cr[j][0] = 0.f; cr[j][1] = 0.f; cr[j][2] = 0.f; cr[j][3] = 0.f;
    }

    const int ar0 = t >> 3;
    const int ak = (t & 7) * 4;
    constexpr int BQ = BN / 4;
    const int br0 = t / BQ;
    const int bn = (t % BQ) * 4;

    float4 pa0, pa1, pb[NBLD];
    pa0 = *(const float4*)&A[(size_t)(m0 + ar0) * K + ak];
    pa1 = *(const float4*)&A[(size_t)(m0 + ar0 + 32) * K + ak];
#pragma unroll
    for (int i = 0; i < NBLD; i++) {
        int kr = br0 + i * (256 / BQ);
        pb[i] = *(const float4*)&B[(size_t)kr * N + n0 + bn];
    }

    const int nch = K / KC;
    for (int ch = 0; ch < nch; ch++) {
        __syncthreads();
        {
            uint4 q;
            q.x = f2tf(pa0.x); q.y = f2tf(pa0.y); q.z = f2tf(pa0.z); q.w = f2tf(pa0.w);
            *(uint4*)&As[ar0][ak] = q;
            q.x = f2tf(pa1.x); q.y = f2tf(pa1.y); q.z = f2tf(pa1.z); q.w = f2tf(pa1.w);
            *(uint4*)&As[ar0 + 32][ak] = q;
#pragma unroll
            for (int i = 0; i < NBLD; i++) {
                int kr = br0 + i * (256 / BQ);
                q.x = f2tf(pb[i].x); q.y = f2tf(pb[i].y);
                q.z = f2tf(pb[i].z); q.w = f2tf(pb[i].w);
                *(uint4*)&Bs[kr][bn] = q;
            }
        }
        if (ch + 1 < nch) {
            int k0 = (ch + 1) * KC;
            pa0 = *(const float4*)&A[(size_t)(m0 + ar0) * K + k0 + ak];
            pa1 = *(const float4*)&A[(size_t)(m0 + ar0 + 32) * K + k0 + ak];
#pragma unroll
            for (int i = 0; i < NBLD; i++) {
                int kr = k0 + br0 + i * (256 / BQ);
                pb[i] = *(const float4*)&B[(size_t)kr * N + n0 + bn];
            }
        }
        __syncthreads();
#pragma unroll
        for (int kk = 0; kk < KC; kk += 8) {
            uint32_t a0 = As[warpM * 16 + gid][kk + tig];
            uint32_t a1 = As[warpM * 16 + gid + 8][kk + tig];
            uint32_t a2 = As[warpM * 16 + gid][kk + tig + 4];
            uint32_t a3 = As[warpM * 16 + gid + 8][kk + tig + 4];
#pragma unroll
            for (int j = 0; j < NT; j++) {
                int nb = warpN * (BN / 2) + j * 8;
                uint32_t b0 = Bs[kk + tig][nb + gid];
                uint32_t b1 = Bs[kk + tig + 4][nb + gid];
                mma_tf32(cr[j], a0, a1, a2, a3, b0, b1);
            }
        }
    }

    const int rb = m0 + warpM * 16 + gid;
#pragma unroll
    for (int j = 0; j < NT; j++) {
        int cb = n0 + warpN * (BN / 2) + j * 8 + tig * 2;
#pragma unroll
        for (int h = 0; h < 2; h++) {
            int m = rb + h * 8;
            float v0 = cr[j][h * 2 + 0];
            float v1 = cr[j][h * 2 + 1];
            if (EPI == 2) {
                int en = xi[m0 >> 9];
                if ((m & 511) == en) {
                    C[(size_t)m * N + cb] = xb[cb];
                    C[(size_t)m * N + cb + 1] = xb[cb + 1];
                } else {
                    C[(size_t)m * N + cb] = v0 + bias[cb];
                    C[(size_t)m * N + cb + 1] = v1 + bias[cb + 1];
                }
            } else if (EPI == 6) {
                ((uint32_t*)C)[(size_t)m * N + cb] = f2tf(v0);
                ((uint32_t*)C)[(size_t)m * N + cb + 1] = f2tf(v1);
            } else if (EPI == 7) {
                float o0 = v0 + bias[cb], o1 = v1 + bias[cb + 1];
                C[(size_t)m * N + cb] = o0;
                C[(size_t)m * N + cb + 1] = o1;
                C2[(size_t)m * N + cb] = o0 + xb[cb];
                C2[(size_t)m * N + cb + 1] = o1 + xb[cb + 1];
            }
        }
    }
}

// --------------- selkey gathered GEMM + removed scatter + pooled-emb scan ------
__global__ void __launch_bounds__(256) k_selkey(const float* __restrict__ ent,
                                                const float* __restrict__ kw,
                                                const float* __restrict__ kb,
                                                const int* __restrict__ sel,
                                                const int* __restrict__ en_arr,
                                                const int* __restrict__ selnum) {
    __shared__ uint32_t AS[64 * 68];
    __shared__ uint32_t BS[64 * 36];   // reused as SK float[64][33] in scan phase
    __shared__ int ssh[64];
    __shared__ int inc[64];
    const int t = threadIdx.x;
    const int b = blockIdx.x;
    const int wid = t >> 5, lane = t & 31;
    const int gid = lane >> 2, tig = lane & 3;
    const int warpM = wid & 3, warpN = wid >> 2;
    const int en = en_arr[b];

    if (t < 64) ssh[t] = sel[b * SEQN + t];
    for (int n = t; n < ENP1; n += 256) g_removed[(size_t)b * ENP1 + n] = 65;
    __syncthreads();
    if (t < 64) atomicMin(&g_removed[(size_t)b * ENP1 + ssh[t]], t + 1);
    // include flags: first occurrence & not after end token
    if (t < 64) {
        int sj = ssh[t];
        bool first = true, endf = (sj == en);
        for (int k = 0; k < t; k++) {
            int sk = ssh[k];
            if (sk == sj) first = false;
            if (sk == en) endf = true;
        }
        inc[t] = (first && !endf) ? 1 : 0;
    }

    float acc[2][4];
    acc[0][0] = acc[0][1] = acc[0][2] = acc[0][3] = 0.f;
    acc[1][0] = acc[1][1] = acc[1][2] = acc[1][3] = 0.f;

    for (int ch = 0; ch < 4; ch++) {
        int k0 = ch * 64;
        __syncthreads();
#pragma unroll
        for (int p = 0; p < 4; p++) {
            int idx = t + p * 256;
            int r = idx >> 4, c4 = (idx & 15) * 4;
            float4 v = *(const float4*)&ent[((size_t)b * ENT + ssh[r]) * 256 + k0 + c4];
            AS[r * 68 + c4 + 0] = f2tf(v.x);
            AS[r * 68 + c4 + 1] = f2tf(v.y);
            AS[r * 68 + c4 + 2] = f2tf(v.z);
            AS[r * 68 + c4 + 3] = f2tf(v.w);
        }
#pragma unroll
        for (int p = 0; p < 2; p++) {
            int idx = t + p * 256;
            int r = idx >> 3, c4 = (idx & 7) * 4;
            float4 v = *(const float4*)&kw[(size_t)(k0 + r) * 32 + c4];
            BS[r * 36 + c4 + 0] = f2tf(v.x);
            BS[r * 36 + c4 + 1] = f2tf(v.y);
            BS[r * 36 + c4 + 2] = f2tf(v.z);
            BS[r * 36 + c4 + 3] = f2tf(v.w);
        }
        __syncthreads();
#pragma unroll
        for (int kk = 0; kk < 64; kk += 8) {
            uint32_t a0 = AS[(warpM * 16 + gid) * 68 + kk + tig];
            uint32_t a1 = AS[(warpM * 16 + gid + 8) * 68 + kk + tig];
            uint32_t a2 = AS[(warpM * 16 + gid) * 68 + kk + tig + 4];
            uint32_t a3 = AS[(warpM * 16 + gid + 8) * 68 + kk + tig + 4];
#pragma unroll
            for (int j = 0; j < 2; j++) {
                int nb = warpN * 16 + j * 8;
                uint32_t b0 = BS[(kk + tig) * 36 + nb + gid];
                uint32_t b1 = BS[(kk + tig + 4) * 36 + nb + gid];
                mma_tf32(acc[j], a0, a1, a2, a3, b0, b1);
            }
        }
    }
    __syncthreads();
    float* SK = (float*)BS;
#pragma unroll
    for (int j = 0; j < 2; j++) {
        int cb = warpN * 16 + j * 8 + tig * 2;
        float b0 = kb[cb], b1 = kb[cb + 1];
#pragma unroll
        for (int h = 0; h < 2; h++) {
            int r = warpM * 16 + gid + h * 8;
            SK[r * 33 + cb] = acc[j][h * 2] + b0;
            SK[r * 33 + cb + 1] = acc[j][h * 2 + 1] + b1;
        }
    }
    __syncthreads();
    if (t < 32) {
        int sn = selnum[b];
        float sum = 0.f;
        int cnt = 0;
        for (int j = 0; j < SEQN; j++) {
            if (inc[j]) {
                sum += SK[j * 33 + t];
                cnt++;
            }
            float denom = (sn != 0 && cnt > 0) ? (float)cnt : 1.f;
            g_selemb[((size_t)j * BSZ + b) * DK + t] = sum / denom;
        }
    }
}

// --------------- tiny converters ----------------------------------------------
__global__ void k_cvt(const float* __restrict__ e1w, const float* __restrict__ q2w) {
    int i = blockIdx.x * 256 + threadIdx.x;
    if (i < 8192) g_e1t[i] = f2tf(e1w[i]);
    else g_q2t[i - 8192] = f2tf(q2w[i - 8192]);
}

// c2 = e2_b @ q1_w (parallel over 8 blocks x 8 k-slices)
__global__ void k_c2(const float* __restrict__ e2b, const float* __restrict__ q1w) {
    __shared__ float part[8][32];
    int t = threadIdx.x;
    int col = blockIdx.x * 32 + (t & 31);
    int ks = t >> 5;
    float acc = 0.f;
    for (int k = ks * 128; k < ks * 128 + 128; k++) acc += e2b[k] * q1w[(size_t)k * DF + col];
    part[ks][t & 31] = acc;
    __syncthreads();
    if (t < 32) {
        float s = 0.f;
#pragma unroll
        for (int p = 0; p < 8; p++) s += part[p][t];
        g_c2[blockIdx.x * 32 + t] = s;
    }
}

// --------------- mega-fused (BM=128): u -> P -> relu -> x -> LN gates ----------
// smem floats: U u32[128][260] @0 (33280) | BS u32 @33280 (10240: E1 / W2chunk / Q2S)
//              SEL u32[128][36] @43520 (4608; xsh float[128][33] alias) | wih @48128 (4096)
#define SMF_FLOATS 52224
__global__ void __launch_bounds__(256, 1)
k_fused(const float* __restrict__ e1b, const float* __restrict__ q2b,
        const float* __restrict__ wih, const float* __restrict__ ln_ig,
        const float* __restrict__ ln_ib) {
    extern __shared__ float sm[];
    uint32_t* U = (uint32_t*)sm;
    uint32_t* BS = (uint32_t*)(sm + 33280);
    uint32_t* SEL = (uint32_t*)(sm + 43520);
    float* xsh = sm + 43520;
    float* wsh = sm + 48128;

    const int t = threadIdx.x;
    const int wid = t >> 5, lane = t & 31;
    const int gid = lane >> 2, tig = lane & 3;
    const int warpM = wid & 3, warpN = wid >> 2;
    const int m0 = blockIdx.x * 128;
    const int step = m0 >> 9;
    const int b0 = m0 & 511;

    if (step == 0) {
        // U = tf32(relu(base))
#pragma unroll 4
        for (int p = 0; p < 32; p++) {
            int idx = t + p * 256;
            int r = idx >> 6, c4 = (idx & 63) * 4;
            float4 v = *(const float4*)&g_base[(size_t)(b0 + r) * 256 + c4];
            uint4 q;
            q.x = f2tf(fmaxf(v.x, 0.f)); q.y = f2tf(fmaxf(v.y, 0.f));
            q.z = f2tf(fmaxf(v.z, 0.f)); q.w = f2tf(fmaxf(v.w, 0.f));
            *(uint4*)&U[r * 260 + c4] = q;
        }
    } else {
        // stage SEL (cvt) + E1 (copy) into BS
#pragma unroll
        for (int p = 0; p < 4; p++) {
            int idx = t + p * 256;
            int r = idx >> 3, c4 = (idx & 7) * 4;
            float4 v = *(const float4*)&g_selemb[(size_t)(m0 - 512 + r) * 32 + c4];
            uint4 q;
            q.x = f2tf(v.x); q.y = f2tf(v.y); q.z = f2tf(v.z); q.w = f2tf(v.w);
            *(uint4*)&SEL[r * 36 + c4] = q;
        }
#pragma unroll
        for (int p = 0; p < 8; p++) {
            int q = t + p * 256;
            int r = q >> 6, c4 = (q & 63) * 4;
            *(uint4*)&BS[r * 264 + c4] = ((const uint4*)g_e1t)[q];
        }
        __syncthreads();

        float acc[2][16][4];
#pragma unroll
        for (int mt = 0; mt < 2; mt++)
#pragma unroll
            for (int j = 0; j < 16; j++) {
                acc[mt][j][0] = 0.f; acc[mt][j][1] = 0.f;
                acc[mt][j][2] = 0.f; acc[mt][j][3] = 0.f;
            }
        // u = selemb @ e1
#pragma unroll
        for (int kk = 0; kk < 32; kk += 8) {
#pragma unroll
            for (int mt = 0; mt < 2; mt++) {
                int rbase = warpM * 32 + mt * 16 + gid;
                uint32_t a0 = SEL[rbase * 36 + kk + tig];
                uint32_t a1 = SEL[(rbase + 8) * 36 + kk + tig];
                uint32_t a2 = SEL[rbase * 36 + kk + tig + 4];
                uint32_t a3 = SEL[(rbase + 8) * 36 + kk + tig + 4];
#pragma unroll
                for (int j = 0; j < 16; j++) {
                    int nb = warpN * 128 + j * 8;
                    uint32_t b0 = BS[(kk + tig) * 264 + nb + gid];
                    uint32_t b1 = BS[(kk + tig + 4) * 264 + nb + gid];
                    mma_tf32(acc[mt][j], a0, a1, a2, a3, b0, b1);
                }
            }
        }
        // U = tf32(relu(u + e1b))
#pragma unroll
        for (int mt = 0; mt < 2; mt++)
#pragma unroll
            for (int j = 0; j < 16; j++) {
                int cb = warpN * 128 + j * 8 + tig * 2;
                float bb0 = e1b[cb], bb1 = e1b[cb + 1];
#pragma unroll
                for (int h = 0; h < 2; h++) {
                    int r = warpM * 32 + mt * 16 + gid + h * 8;
                    U[r * 260 + cb] = f2tf(fmaxf(acc[mt][j][h * 2] + bb0, 0.f));
                    U[r * 260 + cb + 1] = f2tf(fmaxf(acc[mt][j][h * 2 + 1] + bb1, 0.f));
                }
            }
#pragma unroll
        for (int mt = 0; mt < 2; mt++)
#pragma unroll
            for (int j = 0; j < 16; j++) {
                acc[mt][j][0] = 0.f; acc[mt][j][1] = 0.f;
                acc[mt][j][2] = 0.f; acc[mt][j][3] = 0.f;
            }
        // P = U @ W2 (tf32 bits precomputed; reg double-buffered chunks)
        uint4 pw[8];
        const uint4* W2v = (const uint4*)g_W2;
#pragma unroll
        for (int p = 0; p < 8; p++) pw[p] = W2v[t + p * 256];
        for (int ch = 0; ch < 8; ch++) {
            __syncthreads();
#pragma unroll
            for (int p = 0; p < 8; p++) {
                int q = t + p * 256;
                int r = q >> 6, c4 = (q & 63) * 4;
                *(uint4*)&BS[r * 264 + c4] = pw[p];
            }
            if (ch + 1 < 8) {
#pragma unroll
                for (int p = 0; p < 8; p++) pw[p] = W2v[(ch + 1) * 2048 + t + p * 256];
            }
            __syncthreads();
#pragma unroll
            for (int kk = 0; kk < 32; kk += 8) {
                int kg = ch * 32 + kk;
#pragma unroll
                for (int mt = 0; mt < 2; mt++) {
                    int rbase = warpM * 32 + mt * 16 + gid;
                    uint32_t a0 = U[rbase * 260 + kg + tig];
                    uint32_t a1 = U[(rbase + 8) * 260 + kg + tig];
                    uint32_t a2 = U[rbase * 260 + kg + tig + 4];
                    uint32_t a3 = U[(rbase + 8) * 260 + kg + tig + 4];
#pragma unroll
                    for (int j = 0; j < 16; j++) {
                        int nb = warpN * 128 + j * 8;
                        uint32_t b0 = BS[(kk + tig) * 264 + nb + gid];
                        uint32_t b1 = BS[(kk + tig + 4) * 264 + nb + gid];
                        mma_tf32(acc[mt][j], a0, a1, a2, a3, b0, b1);
                    }
                }
            }
        }
        __syncthreads();
        // U = tf32(relu(P + basec))
#pragma unroll
        for (int mt = 0; mt < 2; mt++)
#pragma unroll
            for (int j = 0; j < 16; j++) {
                int cb = warpN * 128 + j * 8 + tig * 2;
#pragma unroll
                for (int h = 0; h < 2; h++) {
                    int r = warpM * 32 + mt * 16 + gid + h * 8;
                    float2 bc = *(const float2*)&g_basec[(size_t)(b0 + r) * 256 + cb];
                    U[r * 260 + cb] = f2tf(fmaxf(acc[mt][j][h * 2] + bc.x, 0.f));
                    U[r * 260 + cb + 1] = f2tf(fmaxf(acc[mt][j][h * 2 + 1] + bc.y, 0.f));
                }
            }
    }
    __syncthreads();

    // stage q2 (copy) + wih
#pragma unroll
    for (int p = 0; p < 8; p++) {
        int q = t + p * 256;
        int r = q >> 3, c4 = (q & 7) * 4;
        *(uint4*)&BS[r * 40 + c4] = ((const uint4*)g_q2t)[q];
    }
    for (int idx = t; idx < 4096; idx += 256) wsh[idx] = wih[idx];
    __syncthreads();

    // x = U @ q2
    {
        float ax[2][2][4];
#pragma unroll
        for (int mt = 0; mt < 2; mt++)
#pragma unroll
            for (int j = 0; j < 2; j++) {
                ax[mt][j][0] = 0.f; ax[mt][j][1] = 0.f;
                ax[mt][j][2] = 0.f; ax[mt][j][3] = 0.f;
            }
#pragma unroll 4
        for (int kk = 0; kk < 256; kk += 8) {
#pragma unroll
            for (int mt = 0; mt < 2; mt++) {
                int rbase = warpM * 32 + mt * 16 + gid;
                uint32_t a0 = U[rbase * 260 + kk + tig];
                uint32_t a1 = U[(rbase + 8) * 260 + kk + tig];
                uint32_t a2 = U[rbase * 260 + kk + tig + 4];
                uint32_t a3 = U[(rbase + 8) * 260 + kk + tig + 4];
#pragma unroll
                for (int j = 0; j < 2; j++) {
                    int nb = warpN * 16 + j * 8;
                    uint32_t b0 = BS[(kk + tig) * 40 + nb + gid];
                    uint32_t b1 = BS[(kk + tig + 4) * 40 + nb + gid];
                    mma_tf32(ax[mt][j], a0, a1, a2, a3, b0, b1);
                }
            }
        }
        __syncthreads();   // xsh aliases SEL; SEL reads long done
#pragma unroll
        for (int mt = 0; mt < 2; mt++)
#pragma unroll
            for (int j = 0; j < 2; j++) {
                int cb = warpN * 16 + j * 8 + tig * 2;
                float qb0 = q2b[cb], qb1 = q2b[cb + 1];
#pragma unroll
                for (int h = 0; h < 2; h++) {
                    int r = warpM * 32 + mt * 16 + gid + h * 8;
                    xsh[r * 33 + cb] = ax[mt][j][h * 2] + qb0;
                    xsh[r * 33 + cb + 1] = ax[mt][j][h * 2 + 1] + qb1;
                }
            }
    }
    __syncthreads();

    // gates = LN(x @ wih)
    {
        float lg[4], lb[4];
#pragma unroll
        for (int g = 0; g < 4; g++) {
            lg[g] = ln_ig[g * 32 + lane];
            lb[g] = ln_ib[g * 32 + lane];
        }
        for (int rr = 0; rr < 16; rr++) {
            int row = wid * 16 + rr;
            float xv = xsh[row * 33 + lane];
            float acg[4] = {0.f, 0.f, 0.f, 0.f};
#pragma unroll
            for (int k = 0; k < 32; k++) {
                float xk = __shfl_sync(0xffffffffu, xv, k);
#pragma unroll
                for (int g = 0; g < 4; g++) acg[g] += xk * wsh[k * 128 + g * 32 + lane];
            }
            float s = acg[0] + acg[1] + acg[2] + acg[3];
            float m = wredsum(s) * (1.f / 128.f);
            float vs = 0.f;
#pragma unroll
            for (int g = 0; g < 4; g++) {
                float d = acg[g] - m;
                vs += d * d;
            }
            float v = wredsum(vs) * (1.f / 128.f);
            float rs = rsqrtf(v + 1e-5f);
#pragma unroll
            for (int g = 0; g < 4; g++)
                g_gx[(size_t)(m0 + row) * 128 + g * 32 + lane] =
                    (acg[g] - m) * rs * lg[g] + lb[g];
        }
    }
}

// ------------------- sequential LN-LSTM (warp/batch) ---------------------------
__global__ void k_lstm(const float* __restrict__ whh, const float* __restrict__ ln_hg,
                       const float* __restrict__ ln_hb, const float* __restrict__ ln_cg,
                       const float* __restrict__ ln_cb) {
    __shared__ float wsh[32 * 128];
    int t = threadIdx.x;
    for (int idx = t; idx < 4096; idx += 256) wsh[idx] = whh[idx];
    __syncthreads();
    int lane = t & 31, w = t >> 5;
    int b = blockIdx.x * 8 + w;
    float h = 0.f, c = 0.f;
    float hg[4], hb[4];
#pragma unroll
    for (int g = 0; g < 4; g++) {
        int cc = g * 32 + lane;
        hg[g] = ln_hg[cc];
        hb[g] = ln_hb[cc];
    }
    float cgm = ln_cg[lane], cbm = ln_cb[lane];
    float gxr[4];
#pragma unroll
    for (int g = 0; g < 4; g++) gxr[g] = g_gx[(size_t)b * 128 + g * 32 + lane];
    for (int i = 0; i < SEQN; i++) {
        float gxn[4];
        if (i + 1 < SEQN) {
            size_t rn = (size_t)(i + 1) * BSZ + b;
#pragma unroll
            for (int g = 0; g < 4; g++) gxn[g] = g_gx[rn * 128 + g * 32 + lane];
        }
        float acc[4] = {0.f, 0.f, 0.f, 0.f};
#pragma unroll
        for (int k = 0; k < 32; k++) {
            float hk = __shfl_sync(0xffffffffu, h, k);
#pragma unroll
            for (int g = 0; g < 4; g++) acc[g] += hk * wsh[k * 128 + g * 32 + lane];
        }
        float s = acc[0] + acc[1] + acc[2] + acc[3];
        float m = wredsum(s) * (1.f / 128.f);
        float vs = 0.f;
#pragma unroll
        for (int g = 0; g < 4; g++) {
            float d = acc[g] - m;
            vs += d * d;
        }
        float v = wredsum(vs) * (1.f / 128.f);
        float rs = rsqrtf(v + 1e-5f);
        float gate[4];
#pragma unroll
        for (int g = 0; g < 4; g++) gate[g] = gxr[g] + (acc[g] - m) * rs * hg[g] + hb[g];
        float ii = 1.f / (1.f + __expf(-gate[0]));
        float ff = 1.f / (1.f + __expf(-gate[1]));
        float gg = tanhf(gate[2]);
        float oo = 1.f / (1.f + __expf(-gate[3]));
        float cn = ff * c + ii * gg;
        float mc = wredsum(cn) * (1.f / 32.f);
        float dc = cn - mc;
        float vc = wredsum(dc * dc) * (1.f / 32.f);
        c = dc * rsqrtf(vc + 1e-5f) * cgm + cbm;
        h = oo * tanhf(c);
        g_q[((size_t)i * BSZ + b) * DK + lane] = h;
#pragma unroll
        for (int g = 0; g < 4; g++) gxr[g] = gxn[g];
    }
}

// ------------------- logits + mask (grid BSZ x 2) -------------------------------
__global__ void k_logits(const int* __restrict__ en_arr, float* __restrict__ out) {
    __shared__ float Qsh[64 * 32];
    __shared__ float Ksh[256 * 34];
    __shared__ int rsh[256];
    int t = threadIdx.x;
    int b = blockIdx.x;
    int tile = blockIdx.y;
    int en = en_arr[b];
    for (int idx = t; idx < 2048; idx += 256) {
        int s = idx >> 5, k = idx & 31;
        Qsh[idx] = g_q[((size_t)s * BSZ + b) * 32 + k];
    }
    const u64* Q2 = (const u64*)Qsh;
    int n0 = tile * 256;
    for (int idx = t; idx < 8192; idx += 256) {
        int n = idx >> 5, k = idx & 31;
        Ksh[n * 34 + k] = g_key[((size_t)b * ENT + n0 + n) * 32 + k];
    }
    rsh[t] = g_removed[(size_t)b * ENP1 + n0 + t];
    __syncthreads();
    u64 kreg[16];
#pragma unroll
    for (int kp = 0; kp < 16; kp++) {
        float2 kk = *(const float2*)&Ksh[t * 34 + kp * 2];
        asm("mov.b64 %0,{%1,%2};" : "=l"(kreg[kp]) : "f"(kk.x), "f"(kk.y));
    }
    int rstep = rsh[t];
    int n = n0 + t;
    for (int s = 0; s < SEQN; s++) {
        u64 a0 = 0ull, a1 = 0ull;
#pragma unroll
        for (int kp = 0; kp < 16; kp += 2) {
            fma2(a0, kreg[kp], Q2[s * 16 + kp]);
            fma2(a1, kreg[kp + 1], Q2[s * 16 + kp + 1]);
        }
        float2 f0 = up2(a0), f1 = up2(a1);
        float dot = (f0.x + f0.y) + (f1.x + f1.y);
        bool keep = (n < en) ? (rstep > s) : ((n == en) ? (s >= 1 && rstep > s) : false);
        out[((size_t)b * SEQN + s) * ENP1 + n] = keep ? dot : -1e9f;
    }
    if (tile == 1 && t < SEQN) out[((size_t)b * SEQN + t) * ENP1 + 512] = -1e9f;
}

// ------------------------------- launch ----------------------------------------
extern "C" void kernel_launch(void* const* d_in, const int* in_sizes, int n_in,
                              void* d_out, int out_size) {
    const float* ent = (const float*)d_in[0];
    const float* ar = (const float*)d_in[1];
    const int* entity_num = (const int*)d_in[2];
    const int* sel = (const int*)d_in[3];
    const int* selnum = (const int*)d_in[4];
    const float* key_w = (const float*)d_in[5];
    const float* key_b = (const float*)d_in[6];
    const float* q1w = (const float*)d_in[7];
    const float* q1b = (const float*)d_in[8];
    const float* q2w = (const float*)d_in[9];
    const float* q2b = (const float*)d_in[10];
    const float* e1w = (const float*)d_in[11];
    const float* e1b = (const float*)d_in[12];
    const float* e2w = (const float*)d_in[13];
    const float* e2b = (const float*)d_in[14];
    const float* endv = (const float*)d_in[15];
    const float* wih = (const float*)d_in[16];
    const float* whh = (const float*)d_in[17];
    const float* ln_ig = (const float*)d_in[18];
    const float* ln_ib = (const float*)d_in[19];
    const float* ln_hg = (const float*)d_in[20];
    const float* ln_hb = (const float*)d_in[21];
    const float* ln_cg = (const float*)d_in[22];
    const float* ln_cb = (const float*)d_in[23];
    float* out = (float*)d_out;

    void *pKey, *pBase, *pBasec, *pW2, *pC2;
    cudaGetSymbolAddress(&pKey, g_key);
    cudaGetSymbolAddress(&pBase, g_base);
    cudaGetSymbolAddress(&pBasec, g_basec);
    cudaGetSymbolAddress(&pW2, g_W2);
    cudaGetSymbolAddress(&pC2, g_c2);

    static cudaStream_t sB = 0, sC = 0, sD = 0;
    static cudaEvent_t eFork = 0, eB = 0, eW2 = 0, eKey = 0;
    if (!sB) {
        int lo, hi;
        cudaDeviceGetStreamPriorityRange(&lo, &hi);
        cudaStreamCreateWithFlags(&sB, cudaStreamNonBlocking);
        cudaStreamCreateWithFlags(&sC, cudaStreamNonBlocking);
        cudaStreamCreateWithPriority(&sD, cudaStreamNonBlocking, lo);  // lowest prio
        cudaEventCreateWithFlags(&eFork, cudaEventDisableTiming);
        cudaEventCreateWithFlags(&eB, cudaEventDisableTiming);
        cudaEventCreateWithFlags(&eW2, cudaEventDisableTiming);
        cudaEventCreateWithFlags(&eKey, cudaEventDisableTiming);
        cudaFuncSetAttribute(k_fused, cudaFuncAttributeMaxDynamicSharedMemorySize,
                             SMF_FLOATS * 4);
    }

    // fork
    cudaEventRecord(eFork, 0);
    cudaStreamWaitEvent(sB, eFork, 0);
    cudaStreamWaitEvent(sC, eFork, 0);
    cudaStreamWaitEvent(sD, eFork, 0);

    // side B: c2 then base (+basec)
    k_c2<<<8, 256, 0, sB>>>(e2b, q1w);
    k_mma<64, 7><<<dim3(BSZ / 64, DF / 64), 256, 0, sB>>>(
        ar, q1w, q1b, (float*)pBase, DIN, DF, (const float*)pC2, nullptr, (float*)pBasec);
    cudaEventRecord(eB, sB);

    // side C: weight tf32 conversions + W2 (tf32 bits out)
    k_cvt<<<64, 256, 0, sC>>>(e1w, q2w);
    k_mma<64, 6><<<dim3(DF / 64, DF / 64), 256, 0, sC>>>(
        e2w, q1w, nullptr, (float*)pW2, DIN, DF, nullptr, nullptr, nullptr);
    cudaEventRecord(eW2, sC);

    // side D (low priority): full key GEMM (only logits needs it)
    k_mma<32, 2><<<dim3(BSZ * ENT / 64, 1), 256, 0, sD>>>(
        ent, key_w, key_b, (float*)pKey, DF, DK, endv, entity_num, nullptr);
    cudaEventRecord(eKey, sD);

    // main: selkey(+removed+emb) -> fused -> lstm -> logits
    k_selkey<<<BSZ, 256>>>(ent, key_w, key_b, sel, entity_num, selnum);
    cudaStreamWaitEvent(0, eB, 0);
    cudaStreamWaitEvent(0, eW2, 0);
    k_fused<<<SEQN * BSZ / 128, 256, SMF_FLOATS * 4>>>(e1b, q2b, wih, ln_ig, ln_ib);
    k_lstm<<<BSZ / 8, 256>>>(whh, ln_hg, ln_hb, ln_cg, ln_cb);
    cudaStreamWaitEvent(0, eKey, 0);
    k_logits<<<dim3(BSZ, 2), 256>>>(entity_num, out);
    (void)in_sizes;
    (void)n_in;
    (void)out_size;
}